// round 5
// baseline (speedup 1.0000x reference)
#include <cuda_runtime.h>
#include <cstdint>

#define N_NODES 50000
#define N_EDGES 640000
#define D 128
#define N_RELS 16
#define N_NT 8
#define TILE 128

#define EG (N_EDGES / TILE + N_RELS)            /* 5016 tiles max for edge gemm */
#define NG ((N_NODES + TILE - 1) / TILE + N_NT) /* 399 tiles max for node gemm */
#define E_PAD (EG * TILE)
#define N_PAD (NG * TILE)

#define SROW 132                        /* padded smem row stride (floats) */
#define EDGE_SMEM (3 * 128 * SROW * 4)  /* sB + sA0 + sA1 = 202752 B */
#define NODE_SMEM (2 * 128 * SROW * 4)  /* 135168 B */
#define EDGE_GRID 148
#define CHUNK 8

/* ------------------------------ scratch ------------------------------ */
__device__ int   g_counts[N_NODES * N_RELS];
__device__ int   g_rel_cnt[N_RELS];
__device__ int   g_rel_cur[N_RELS];
__device__ int   g_nt_cnt[N_NT];
__device__ int   g_nt_cur[N_NT];
__device__ int   g_eperm[E_PAD];
__device__ int   g_nperm[N_PAD];
__device__ float g_agg[N_NODES * D];
__device__ int   g_ntiles[2];
__device__ float g_WT[N_RELS * D * D];   /* W_edge^T: [r][f][d], tf32-rounded */
__device__ float g_WnT[N_NT * D * D];    /* W_node^T */
__device__ float g_featsR[N_NODES * D];  /* feats, tf32-rna-rounded */
__device__ int   g_ticket;
__device__ int   g_barrier_cnt;

/* ------------------------------ helpers ------------------------------ */
__device__ __forceinline__ uint32_t tf32r(float x) {
    uint32_t r;
    asm("cvt.rna.tf32.f32 %0, %1;" : "=r"(r) : "f"(x));
    return r;
}
__device__ __forceinline__ uint32_t smem_u32(const void* p) {
    uint32_t a;
    asm("{ .reg .u64 t; cvta.to.shared.u64 t, %1; cvt.u32.u64 %0, t; }" : "=r"(a) : "l"(p));
    return a;
}
__device__ __forceinline__ void cpa16(uint32_t dstS, const void* src) {
    asm volatile("cp.async.ca.shared.global [%0], [%1], 16;" :: "r"(dstS), "l"(src));
}
__device__ __forceinline__ void mma8(float* c, const uint32_t* a, const uint32_t* b) {
    asm volatile(
        "mma.sync.aligned.m16n8k8.row.col.f32.tf32.tf32.f32 "
        "{%0,%1,%2,%3}, {%4,%5,%6,%7}, {%8,%9}, {%0,%1,%2,%3};"
        : "+f"(c[0]), "+f"(c[1]), "+f"(c[2]), "+f"(c[3])
        : "r"(a[0]), "r"(a[1]), "r"(a[2]), "r"(a[3]), "r"(b[0]), "r"(b[1]));
}
__device__ __forceinline__ void red4(float* p, float x, float y, float z, float w) {
    asm volatile("red.global.add.v4.f32 [%0], {%1,%2,%3,%4};"
                 :: "l"(p), "f"(x), "f"(y), "f"(z), "f"(w) : "memory");
}
/* grid-wide barrier for k_sortall (148 co-resident blocks) */
__device__ __forceinline__ void gsync(int phase) {
    __syncthreads();
    if (threadIdx.x == 0) {
        __threadfence();
        atomicAdd(&g_barrier_cnt, 1);
        while (atomicAdd(&g_barrier_cnt, 0) < EDGE_GRID * phase) {}
    }
    __syncthreads();
}

/* ------------------------------ setup: zero + round + transpose ------------------------------ */
__global__ void k_zerowt(const float* __restrict__ feats, const float* __restrict__ We,
                         const float* __restrict__ Wn) {
    int i = blockIdx.x * blockDim.x + threadIdx.x;
    int stride = gridDim.x * blockDim.x;
    for (int j = i; j < N_NODES * D; j += stride) {
        g_agg[j] = 0.0f;
        g_featsR[j] = __uint_as_float(tf32r(feats[j]));
    }
    for (int j = i; j < N_NODES * N_RELS; j += stride) g_counts[j] = 0;
    for (int j = i; j < E_PAD; j += stride) g_eperm[j] = -1;
    for (int j = i; j < N_PAD; j += stride) g_nperm[j] = -1;
    if (i < N_RELS) g_rel_cnt[i] = 0;
    if (i < N_NT) g_nt_cnt[i] = 0;
    if (i == 0) g_barrier_cnt = 0;
    /* transpose weights: coalesced write Wdst[f*128+d], strided read (L2-resident) */
    for (int j = i; j < (N_RELS + N_NT) * D * D; j += stride) {
        int m = j >> 14, lin = j & 16383;
        int f = lin >> 7, d = lin & 127;
        if (m < N_RELS)
            g_WT[(size_t)m * D * D + f * D + d] =
                __uint_as_float(tf32r(We[(size_t)m * D * D + d * D + f]));
        else
            g_WnT[(size_t)(m - N_RELS) * D * D + f * D + d] =
                __uint_as_float(tf32r(Wn[(size_t)(m - N_RELS) * D * D + d * D + f]));
    }
}

/* ------------------------------ setup: hist + scan + scatter (one kernel) ------------------------------ */
__global__ __launch_bounds__(256, 1) void k_sortall(
    const int* __restrict__ dst, const int* __restrict__ etypes,
    const int* __restrict__ ntypes) {
    __shared__ int sh[N_RELS + N_NT];
    __shared__ int s_cnt[N_RELS], s_base[N_RELS];
    const int tid = threadIdx.x;

    /* phase 1: histograms */
    if (tid < N_RELS + N_NT) sh[tid] = 0;
    __syncthreads();
    int i = blockIdx.x * blockDim.x + tid;
    int stride = gridDim.x * blockDim.x;
    for (int e = i; e < N_EDGES; e += stride) {
        int t = etypes[e];
        atomicAdd(&sh[t], 1);
        atomicAdd(&g_counts[dst[e] * N_RELS + t], 1);
    }
    for (int n = i; n < N_NODES; n += stride) atomicAdd(&sh[N_RELS + ntypes[n]], 1);
    __syncthreads();
    if (tid < N_RELS) atomicAdd(&g_rel_cnt[tid], sh[tid]);
    else if (tid < N_RELS + N_NT) atomicAdd(&g_nt_cnt[tid - N_RELS], sh[tid]);

    gsync(1);

    /* phase 2: scan (single thread) */
    if (blockIdx.x == 0 && tid == 0) {
        int off = 0;
        for (int t = 0; t < N_RELS; t++) {
            g_rel_cur[t] = off;
            off += ((g_rel_cnt[t] + TILE - 1) / TILE) * TILE;
        }
        g_ntiles[0] = off / TILE;
        off = 0;
        for (int t = 0; t < N_NT; t++) {
            g_nt_cur[t] = off;
            off += ((g_nt_cnt[t] + TILE - 1) / TILE) * TILE;
        }
        g_ntiles[1] = off / TILE;
        g_ticket = 0;
        __threadfence();
    }

    gsync(2);

    /* phase 3: chunked stable scatter */
    const int CH = 2048;
    int nch = (N_EDGES + CH - 1) / CH;
    for (int ch = blockIdx.x; ch < nch; ch += gridDim.x) {
        int lo = ch * CH, hi = min(lo + CH, N_EDGES);
        if (tid < N_RELS) s_cnt[tid] = 0;
        __syncthreads();
        for (int e = lo + tid; e < hi; e += blockDim.x) atomicAdd(&s_cnt[etypes[e]], 1);
        __syncthreads();
        if (tid < N_RELS) {
            s_base[tid] = atomicAdd(&g_rel_cur[tid], s_cnt[tid]);
            s_cnt[tid] = 0;
        }
        __syncthreads();
        for (int e = lo + tid; e < hi; e += blockDim.x) {
            int t = etypes[e];
            g_eperm[s_base[t] + atomicAdd(&s_cnt[t], 1)] = e;
        }
        __syncthreads();
    }
    nch = (N_NODES + CH - 1) / CH;
    for (int ch = blockIdx.x; ch < nch; ch += gridDim.x) {
        int lo = ch * CH, hi = min(lo + CH, N_NODES);
        if (tid < N_NT) s_cnt[tid] = 0;
        __syncthreads();
        for (int n = lo + tid; n < hi; n += blockDim.x) atomicAdd(&s_cnt[ntypes[n]], 1);
        __syncthreads();
        if (tid < N_NT) {
            s_base[tid] = atomicAdd(&g_nt_cur[tid], s_cnt[tid]);
            s_cnt[tid] = 0;
        }
        __syncthreads();
        for (int n = lo + tid; n < hi; n += blockDim.x) {
            int t = ntypes[n];
            g_nperm[s_base[t] + atomicAdd(&s_cnt[t], 1)] = n;
        }
        __syncthreads();
    }
}

__global__ void k_nop() {}

/* ------------------------------ persistent ticket-based edge GEMM ------------------------------ */
__global__ __launch_bounds__(256, 1) void k_edge_p(
    const float* __restrict__ b_edge, const int* __restrict__ src,
    const int* __restrict__ dst, const int* __restrict__ etypes) {
    extern __shared__ float smf[];
    float* sB = smf;                       /* [128][SROW] */
    float* sAbuf[2] = {smf + 128 * SROW, smf + 2 * 128 * SROW};

    __shared__ int sDst[2][TILE];
    __shared__ float sInv[2][TILE];
    __shared__ int sRel[2];
    __shared__ float sBias[TILE];
    __shared__ int sChunk;

    const int ntiles = g_ntiles[0];
    const int tid = threadIdx.x, wid = tid >> 5, lane = tid & 31;
    const int wm = wid & 1, wn = wid >> 1;
    const int r_base = wm * 64, c_base = wn * 32;
    const int lq = lane >> 2, lr = lane & 3;

    auto prefetch = [&](int t) {
        int b = t & 1;
        int r = tid >> 1, h = tid & 1;
        int e = g_eperm[t * TILE + r];
        int s = (e >= 0) ? src[e] : 0;
        const float* gp = g_featsR + (size_t)s * D + h * 64;
        uint32_t sa = smem_u32(sAbuf[b] + r * SROW + h * 64);
#pragma unroll
        for (int c = 0; c < 16; c++) cpa16(sa + c * 16, gp + c * 4);
        asm volatile("cp.async.commit_group;" ::: "memory");
        if (h == 0) {
            int dn = -1;
            float inv = 0.0f;
            if (e >= 0) {
                dn = dst[e];
                int et = etypes[e];
                inv = 1.0f / (float)g_counts[dn * N_RELS + et];
                if (r == 0) sRel[b] = et;
            }
            sDst[b][r] = dn;
            sInv[b][r] = inv;
        }
    };

    int cur_rel = -1;
    for (;;) {
        if (tid == 0) sChunk = atomicAdd(&g_ticket, 1);
        __syncthreads();
        int t0 = sChunk * CHUNK;
        if (t0 >= ntiles) break;
        int t1 = min(t0 + CHUNK, ntiles);
        prefetch(t0);

        for (int t = t0; t < t1; t++) {
            const int b = t & 1;
            if (t + 1 < t1) {
                prefetch(t + 1);
                asm volatile("cp.async.wait_group 1;" ::: "memory");
            } else {
                asm volatile("cp.async.wait_group 0;" ::: "memory");
            }
            __syncthreads();

            const int rel = sRel[b];
            if (rel != cur_rel) {
                cur_rel = rel;
                const float* Wr = g_WT + (size_t)rel * D * D;
#pragma unroll
                for (int i2 = 0; i2 < 16; i2++) {
                    int lin = tid + 256 * i2;
                    int f = lin >> 5, kq = lin & 31;
                    *(float4*)(sB + f * SROW + kq * 4) = *(const float4*)(Wr + f * D + kq * 4);
                }
                if (tid < TILE) sBias[tid] = b_edge[rel * D + tid];
                __syncthreads();
            }

            /* mainloop */
            const uint32_t* sAu = (const uint32_t*)sAbuf[b];
            const uint32_t* sBu = (const uint32_t*)sB;
            float acc[4][4][4];
#pragma unroll
            for (int mt = 0; mt < 4; mt++)
#pragma unroll
                for (int nt = 0; nt < 4; nt++)
#pragma unroll
                    for (int j = 0; j < 4; j++) acc[mt][nt][j] = 0.0f;

#pragma unroll 4
            for (int k0 = 0; k0 < 16; k0++) {
                const int kk = k0 * 8 + lr;
                uint32_t a[4][4], bb[4][2];
#pragma unroll
                for (int mt = 0; mt < 4; mt++) {
                    int row = r_base + mt * 16 + lq;
                    a[mt][0] = sAu[row * SROW + kk];
                    a[mt][1] = sAu[(row + 8) * SROW + kk];
                    a[mt][2] = sAu[row * SROW + kk + 4];
                    a[mt][3] = sAu[(row + 8) * SROW + kk + 4];
                }
#pragma unroll
                for (int nt = 0; nt < 4; nt++) {
                    int n = c_base + nt * 8 + lq;
                    bb[nt][0] = sBu[n * SROW + kk];
                    bb[nt][1] = sBu[n * SROW + kk + 4];
                }
#pragma unroll
                for (int mt = 0; mt < 4; mt++)
#pragma unroll
                    for (int nt = 0; nt < 4; nt++) mma8(acc[mt][nt], a[mt], bb[nt]);
            }
            __syncthreads(); /* all done reading sA[b] */

            /* stage (acc + bias) * inv into the freed A buffer */
            float* sOut = sAbuf[b];
#pragma unroll
            for (int mt = 0; mt < 4; mt++)
#pragma unroll
                for (int h = 0; h < 2; h++) {
                    int rr = r_base + mt * 16 + lq + h * 8;
                    float inv = sInv[b][rr];
#pragma unroll
                    for (int nt = 0; nt < 4; nt++) {
                        int col = c_base + nt * 8 + lr * 2;
                        float2 v;
                        v.x = (acc[mt][nt][h * 2 + 0] + sBias[col]) * inv;
                        v.y = (acc[mt][nt][h * 2 + 1] + sBias[col + 1]) * inv;
                        *(float2*)(sOut + rr * SROW + col) = v;
                    }
                }
            __syncthreads();

            /* scatter: 2 threads per row, 16x red.v4 */
            {
                int r = tid >> 1, half = tid & 1;
                int dn = sDst[b][r];
                if (dn >= 0) {
                    float* gp = g_agg + (size_t)dn * D + half * 64;
                    const float* sp = sOut + r * SROW + half * 64;
#pragma unroll
                    for (int m = 0; m < 16; m++) {
                        float4 v = *(const float4*)(sp + 4 * m);
                        red4(gp + 4 * m, v.x, v.y, v.z, v.w);
                    }
                }
            }
            __syncthreads(); /* sOut free before next prefetch overwrites it */
        }
    }
}

/* ------------------------------ mma.sync node GEMM + residual + relu ------------------------------ */
__global__ __launch_bounds__(256, 1) void k_node_mma(
    const float* __restrict__ b_node, const int* __restrict__ ntypes,
    float* __restrict__ out) {
    if ((int)blockIdx.x >= g_ntiles[1]) return;

    extern __shared__ float smf[];
    float* sA = smf;
    float* sB = smf + 128 * SROW;
    const uint32_t* sAu = (const uint32_t*)sA;
    const uint32_t* sBu = (const uint32_t*)sB;

    __shared__ int sNode[TILE];
    __shared__ float sBias[TILE];
    __shared__ int sNt;

    const int tid = threadIdx.x, wid = tid >> 5, lane = tid & 31;
    const int base = blockIdx.x * TILE;

    if (tid < TILE) {
        int n = g_nperm[base + tid];
        sNode[tid] = n;
        if (tid == 0) sNt = ntypes[n]; /* row 0 of a live tile is always valid */
    }
    __syncthreads();
    const int nt_ = sNt;
    if (tid < TILE) sBias[tid] = b_node[nt_ * D + tid];

    {
        int r = tid >> 1, half = tid & 1;
        int n = sNode[r];
        const float4* fp = (const float4*)(g_featsR + (size_t)(n >= 0 ? n : 0) * D) + half * 16;
        float* ap = sA + r * SROW + half * 64;
#pragma unroll
        for (int i = 0; i < 16; i++) *(float4*)(ap + i * 4) = fp[i];
    }
    {
        const float* Wr = g_WnT + (size_t)nt_ * D * D;
#pragma unroll
        for (int i = 0; i < 16; i++) {
            int lin = tid + 256 * i;
            int f = lin >> 5, kq = lin & 31;
            *(float4*)(sB + f * SROW + kq * 4) = *(const float4*)(Wr + f * D + kq * 4);
        }
    }
    __syncthreads();

    const int wm = wid & 1, wn = wid >> 1;
    const int r_base = wm * 64, c_base = wn * 32;
    const int lq = lane >> 2, lr = lane & 3;

    float acc[4][4][4];
#pragma unroll
    for (int mt = 0; mt < 4; mt++)
#pragma unroll
        for (int ntl = 0; ntl < 4; ntl++)
#pragma unroll
            for (int j = 0; j < 4; j++) acc[mt][ntl][j] = 0.0f;

#pragma unroll 4
    for (int k0 = 0; k0 < 16; k0++) {
        const int kk = k0 * 8 + lr;
        uint32_t a[4][4], b[4][2];
#pragma unroll
        for (int mt = 0; mt < 4; mt++) {
            int row = r_base + mt * 16 + lq;
            a[mt][0] = sAu[row * SROW + kk];
            a[mt][1] = sAu[(row + 8) * SROW + kk];
            a[mt][2] = sAu[row * SROW + kk + 4];
            a[mt][3] = sAu[(row + 8) * SROW + kk + 4];
        }
#pragma unroll
        for (int ntl = 0; ntl < 4; ntl++) {
            int n = c_base + ntl * 8 + lq;
            b[ntl][0] = sBu[n * SROW + kk];
            b[ntl][1] = sBu[n * SROW + kk + 4];
        }
#pragma unroll
        for (int mt = 0; mt < 4; mt++)
#pragma unroll
            for (int ntl = 0; ntl < 4; ntl++) mma8(acc[mt][ntl], a[mt], b[ntl]);
    }

    /* epilogue: relu(acc + bias + agg) -> out */
#pragma unroll
    for (int mt = 0; mt < 4; mt++) {
        int row0 = r_base + mt * 16 + lq;
#pragma unroll
        for (int h = 0; h < 2; h++) {
            int rr = row0 + h * 8;
            int n = sNode[rr];
            if (n < 0) continue;
            const float* ab = g_agg + (size_t)n * D;
            float* ob = out + (size_t)n * D;
#pragma unroll
            for (int ntl = 0; ntl < 4; ntl++) {
                int col = c_base + ntl * 8 + lr * 2;
                float2 ag = *(const float2*)(ab + col);
                float2 o;
                o.x = fmaxf(acc[mt][ntl][h * 2 + 0] + sBias[col] + ag.x, 0.0f);
                o.y = fmaxf(acc[mt][ntl][h * 2 + 1] + sBias[col + 1] + ag.y, 0.0f);
                *(float2*)(ob + col) = o;
            }
        }
    }
}

/* ------------------------------ launch ------------------------------ */
extern "C" void kernel_launch(void* const* d_in, const int* in_sizes, int n_in,
                              void* d_out, int out_size) {
    const float* feats  = (const float*)d_in[0];
    const float* W_edge = (const float*)d_in[1];
    const float* b_edge = (const float*)d_in[2];
    const float* W_node = (const float*)d_in[3];
    const float* b_node = (const float*)d_in[4];
    const int* src    = (const int*)d_in[5];
    const int* dst    = (const int*)d_in[6];
    const int* ntypes = (const int*)d_in[7];
    const int* etypes = (const int*)d_in[8];
    float* out = (float*)d_out;
    (void)in_sizes; (void)n_in; (void)out_size;

    cudaFuncSetAttribute(k_edge_p, cudaFuncAttributeMaxDynamicSharedMemorySize, EDGE_SMEM);
    cudaFuncSetAttribute(k_node_mma, cudaFuncAttributeMaxDynamicSharedMemorySize, NODE_SMEM);

    k_zerowt<<<1024, 256>>>(feats, W_edge, W_node);
    k_sortall<<<EDGE_GRID, 256>>>(dst, etypes, ntypes);
    k_nop<<<1, 1>>>();
    k_edge_p<<<EDGE_GRID, 256, EDGE_SMEM>>>(b_edge, src, dst, etypes);
    k_node_mma<<<NG, 256, NODE_SMEM>>>(b_node, ntypes, out);
}

// round 6
// speedup vs baseline: 1.1021x; 1.1021x over previous
#include <cuda_runtime.h>
#include <cstdint>

#define N_NODES 50000
#define N_EDGES 640000
#define D 128
#define N_RELS 16
#define N_NT 8
#define TILE 128

#define EG (N_EDGES / TILE + N_RELS)
#define NG ((N_NODES + TILE - 1) / TILE + N_NT)
#define E_PAD (EG * TILE)
#define N_PAD (NG * TILE)

#define SROW 132
#define EDGE_SMEM (3 * 128 * SROW * 4)  /* sB + sA0 + sA1 = 202752 B */
#define NODE_SMEM (2 * 128 * SROW * 4)
#define EDGE_GRID 148
#define CHUNK 8

/* ------------------------------ scratch ------------------------------ */
__device__ int   g_counts[N_NODES * N_RELS];
__device__ int   g_rel_cnt[N_RELS];
__device__ int   g_rel_cur[N_RELS];
__device__ int   g_nt_cnt[N_NT];
__device__ int   g_nt_cur[N_NT];
__device__ int   g_eperm[E_PAD];
__device__ int   g_nperm[N_PAD];
__device__ float g_agg[N_NODES * D];
__device__ int   g_ntiles[2];
__device__ float g_WT[N_RELS * D * D];
__device__ float g_WnT[N_NT * D * D];
__device__ float g_featsR[N_NODES * D];
__device__ int   g_ticket;
__device__ int   g_barrier_cnt;

/* ------------------------------ helpers ------------------------------ */
__device__ __forceinline__ uint32_t tf32r(float x) {
    uint32_t r;
    asm("cvt.rna.tf32.f32 %0, %1;" : "=r"(r) : "f"(x));
    return r;
}
__device__ __forceinline__ uint32_t smem_u32(const void* p) {
    uint32_t a;
    asm("{ .reg .u64 t; cvta.to.shared.u64 t, %1; cvt.u32.u64 %0, t; }" : "=r"(a) : "l"(p));
    return a;
}
__device__ __forceinline__ void cpa16(uint32_t dstS, const void* src) {
    asm volatile("cp.async.ca.shared.global [%0], [%1], 16;" :: "r"(dstS), "l"(src));
}
__device__ __forceinline__ void mma8(float* c, const uint32_t* a, const uint32_t* b) {
    asm volatile(
        "mma.sync.aligned.m16n8k8.row.col.f32.tf32.tf32.f32 "
        "{%0,%1,%2,%3}, {%4,%5,%6,%7}, {%8,%9}, {%0,%1,%2,%3};"
        : "+f"(c[0]), "+f"(c[1]), "+f"(c[2]), "+f"(c[3])
        : "r"(a[0]), "r"(a[1]), "r"(a[2]), "r"(a[3]), "r"(b[0]), "r"(b[1]));
}
__device__ __forceinline__ void red2(float* p, float x, float y) {
    asm volatile("red.global.add.v2.f32 [%0], {%1,%2};" :: "l"(p), "f"(x), "f"(y) : "memory");
}
__device__ __forceinline__ void gsync(int phase) {
    __syncthreads();
    if (threadIdx.x == 0) {
        __threadfence();
        atomicAdd(&g_barrier_cnt, 1);
        while (atomicAdd(&g_barrier_cnt, 0) < EDGE_GRID * phase) {}
    }
    __syncthreads();
}

/* ------------------------------ setup: zero + round + transpose ------------------------------ */
__global__ void k_zerowt(const float* __restrict__ feats, const float* __restrict__ We,
                         const float* __restrict__ Wn) {
    int i = blockIdx.x * blockDim.x + threadIdx.x;
    int stride = gridDim.x * blockDim.x;
    for (int j = i; j < N_NODES * D; j += stride) {
        g_agg[j] = 0.0f;
        g_featsR[j] = __uint_as_float(tf32r(feats[j]));
    }
    for (int j = i; j < N_NODES * N_RELS; j += stride) g_counts[j] = 0;
    for (int j = i; j < E_PAD; j += stride) g_eperm[j] = -1;
    for (int j = i; j < N_PAD; j += stride) g_nperm[j] = -1;
    if (i < N_RELS) g_rel_cnt[i] = 0;
    if (i < N_NT) g_nt_cnt[i] = 0;
    if (i == 0) g_barrier_cnt = 0;
    for (int j = i; j < (N_RELS + N_NT) * D * D; j += stride) {
        int m = j >> 14, lin = j & 16383;
        int f = lin >> 7, d = lin & 127;
        if (m < N_RELS)
            g_WT[(size_t)m * D * D + f * D + d] =
                __uint_as_float(tf32r(We[(size_t)m * D * D + d * D + f]));
        else
            g_WnT[(size_t)(m - N_RELS) * D * D + f * D + d] =
                __uint_as_float(tf32r(Wn[(size_t)(m - N_RELS) * D * D + d * D + f]));
    }
}

/* ------------------------------ setup: hist + scan + scatter ------------------------------ */
__global__ __launch_bounds__(256, 1) void k_sortall(
    const int* __restrict__ dst, const int* __restrict__ etypes,
    const int* __restrict__ ntypes) {
    __shared__ int sh[N_RELS + N_NT];
    __shared__ int s_cnt[N_RELS], s_base[N_RELS];
    const int tid = threadIdx.x;

    if (tid < N_RELS + N_NT) sh[tid] = 0;
    __syncthreads();
    int i = blockIdx.x * blockDim.x + tid;
    int stride = gridDim.x * blockDim.x;
    for (int e = i; e < N_EDGES; e += stride) {
        int t = etypes[e];
        atomicAdd(&sh[t], 1);
        atomicAdd(&g_counts[dst[e] * N_RELS + t], 1);
    }
    for (int n = i; n < N_NODES; n += stride) atomicAdd(&sh[N_RELS + ntypes[n]], 1);
    __syncthreads();
    if (tid < N_RELS) atomicAdd(&g_rel_cnt[tid], sh[tid]);
    else if (tid < N_RELS + N_NT) atomicAdd(&g_nt_cnt[tid - N_RELS], sh[tid]);

    gsync(1);

    if (blockIdx.x == 0 && tid == 0) {
        int off = 0;
        for (int t = 0; t < N_RELS; t++) {
            g_rel_cur[t] = off;
            off += ((g_rel_cnt[t] + TILE - 1) / TILE) * TILE;
        }
        g_ntiles[0] = off / TILE;
        off = 0;
        for (int t = 0; t < N_NT; t++) {
            g_nt_cur[t] = off;
            off += ((g_nt_cnt[t] + TILE - 1) / TILE) * TILE;
        }
        g_ntiles[1] = off / TILE;
        g_ticket = 0;
        __threadfence();
    }

    gsync(2);

    const int CH = 2048;
    int nch = (N_EDGES + CH - 1) / CH;
    for (int ch = blockIdx.x; ch < nch; ch += gridDim.x) {
        int lo = ch * CH, hi = min(lo + CH, N_EDGES);
        if (tid < N_RELS) s_cnt[tid] = 0;
        __syncthreads();
        for (int e = lo + tid; e < hi; e += blockDim.x) atomicAdd(&s_cnt[etypes[e]], 1);
        __syncthreads();
        if (tid < N_RELS) {
            s_base[tid] = atomicAdd(&g_rel_cur[tid], s_cnt[tid]);
            s_cnt[tid] = 0;
        }
        __syncthreads();
        for (int e = lo + tid; e < hi; e += blockDim.x) {
            int t = etypes[e];
            g_eperm[s_base[t] + atomicAdd(&s_cnt[t], 1)] = e;
        }
        __syncthreads();
    }
    nch = (N_NODES + CH - 1) / CH;
    for (int ch = blockIdx.x; ch < nch; ch += gridDim.x) {
        int lo = ch * CH, hi = min(lo + CH, N_NODES);
        if (tid < N_NT) s_cnt[tid] = 0;
        __syncthreads();
        for (int n = lo + tid; n < hi; n += blockDim.x) atomicAdd(&s_cnt[ntypes[n]], 1);
        __syncthreads();
        if (tid < N_NT) {
            s_base[tid] = atomicAdd(&g_nt_cur[tid], s_cnt[tid]);
            s_cnt[tid] = 0;
        }
        __syncthreads();
        for (int n = lo + tid; n < hi; n += blockDim.x) {
            int t = ntypes[n];
            g_nperm[s_base[t] + atomicAdd(&s_cnt[t], 1)] = n;
        }
        __syncthreads();
    }
}

__global__ void k_nop() {}

/* ------------------------------ persistent edge GEMM: 512 thr / 16 warps ------------------------------ */
/* Warp grid 4m x 4n, warp tile 32x32 (2 m16 x 4 n8). Epilogue directly from
 * accumulators via red.v2; per-tile meta snapshot to regs so only 2 barriers/tile. */
__global__ __launch_bounds__(512, 1) void k_edge_p(
    const float* __restrict__ b_edge, const int* __restrict__ src,
    const int* __restrict__ dst, const int* __restrict__ etypes) {
    extern __shared__ float smf[];
    float* sB = smf;
    float* sAbuf[2] = {smf + 128 * SROW, smf + 2 * 128 * SROW};

    __shared__ int sDst[2][TILE];
    __shared__ float sInv[2][TILE];
    __shared__ int sRel[2];
    __shared__ float sBias[TILE];
    __shared__ int sChunk;

    const int ntiles = g_ntiles[0];
    const int tid = threadIdx.x, wid = tid >> 5, lane = tid & 31;
    const int wm = wid & 3, wn = wid >> 2;
    const int r_base = wm * 32, c_base = wn * 32;
    const int lq = lane >> 2, lr = lane & 3;

    auto prefetch = [&](int t) {
        int b = t & 1;
        int r = tid >> 2, q = tid & 3;
        int e = g_eperm[t * TILE + r];
        int s = (e >= 0) ? src[e] : 0;
        const float* gp = g_featsR + (size_t)s * D + q * 32;
        uint32_t sa = smem_u32(sAbuf[b] + r * SROW + q * 32);
#pragma unroll
        for (int c = 0; c < 8; c++) cpa16(sa + c * 16, gp + c * 4);
        asm volatile("cp.async.commit_group;" ::: "memory");
        if (q == 0) {
            int dn = -1;
            float inv = 0.0f;
            if (e >= 0) {
                dn = dst[e];
                int et = etypes[e];
                inv = 1.0f / (float)g_counts[dn * N_RELS + et];
                if (r == 0) sRel[b] = et;
            }
            sDst[b][r] = dn;
            sInv[b][r] = inv;
        }
    };

    int cur_rel = -1;
    for (;;) {
        if (tid == 0) sChunk = atomicAdd(&g_ticket, 1);
        __syncthreads();
        int t0 = sChunk * CHUNK;
        if (t0 >= ntiles) break;
        int t1 = min(t0 + CHUNK, ntiles);
        prefetch(t0);

        for (int t = t0; t < t1; t++) {
            const int b = t & 1;
            if (t + 1 < t1) {
                prefetch(t + 1);
                asm volatile("cp.async.wait_group 1;" ::: "memory");
            } else {
                asm volatile("cp.async.wait_group 0;" ::: "memory");
            }
            __syncthreads();  /* cp.async data + meta visible; prior epilogue done */

            const int rel = sRel[b];
            if (rel != cur_rel) {
                cur_rel = rel;
                const float* Wr = g_WT + (size_t)rel * D * D;
#pragma unroll
                for (int i2 = 0; i2 < 8; i2++) {
                    int lin = tid + 512 * i2;
                    int f = lin >> 5, kq = lin & 31;
                    *(float4*)(sB + f * SROW + kq * 4) = *(const float4*)(Wr + f * D + kq * 4);
                }
                if (tid < TILE) sBias[tid] = b_edge[rel * D + tid];
                __syncthreads();
            }

            const uint32_t* sAu = (const uint32_t*)sAbuf[b];
            const uint32_t* sBu = (const uint32_t*)sB;
            float acc[2][4][4];
#pragma unroll
            for (int mt = 0; mt < 2; mt++)
#pragma unroll
                for (int nt = 0; nt < 4; nt++)
#pragma unroll
                    for (int j = 0; j < 4; j++) acc[mt][nt][j] = 0.0f;

#pragma unroll 4
            for (int k0 = 0; k0 < 16; k0++) {
                const int kk = k0 * 8 + lr;
                uint32_t a[2][4], bb[4][2];
#pragma unroll
                for (int mt = 0; mt < 2; mt++) {
                    int row = r_base + mt * 16 + lq;
                    a[mt][0] = sAu[row * SROW + kk];
                    a[mt][1] = sAu[(row + 8) * SROW + kk];
                    a[mt][2] = sAu[row * SROW + kk + 4];
                    a[mt][3] = sAu[(row + 8) * SROW + kk + 4];
                }
#pragma unroll
                for (int nt = 0; nt < 4; nt++) {
                    int n = c_base + nt * 8 + lq;
                    bb[nt][0] = sBu[n * SROW + kk];
                    bb[nt][1] = sBu[n * SROW + kk + 4];
                }
#pragma unroll
                for (int mt = 0; mt < 2; mt++)
#pragma unroll
                    for (int nt = 0; nt < 4; nt++) mma8(acc[mt][nt], a[mt], bb[nt]);
            }

            /* snapshot meta + bias to regs, then release smem for next prefetch */
            int dnr[2][2];
            float invr[2][2], bx[4], by[4];
#pragma unroll
            for (int mt = 0; mt < 2; mt++)
#pragma unroll
                for (int h = 0; h < 2; h++) {
                    int rr = r_base + mt * 16 + lq + h * 8;
                    dnr[mt][h] = sDst[b][rr];
                    invr[mt][h] = sInv[b][rr];
                }
#pragma unroll
            for (int nt = 0; nt < 4; nt++) {
                int col = c_base + nt * 8 + lr * 2;
                bx[nt] = sBias[col];
                by[nt] = sBias[col + 1];
            }
            __syncthreads();  /* all reads of sA[b]/meta done */

            /* epilogue: register-only, fire-and-forget atomics */
#pragma unroll
            for (int mt = 0; mt < 2; mt++)
#pragma unroll
                for (int h = 0; h < 2; h++) {
                    int dn = dnr[mt][h];
                    if (dn < 0) continue;
                    float inv = invr[mt][h];
                    float* gb = g_agg + (size_t)dn * D;
#pragma unroll
                    for (int nt = 0; nt < 4; nt++) {
                        int col = c_base + nt * 8 + lr * 2;
                        float x = (acc[mt][nt][h * 2 + 0] + bx[nt]) * inv;
                        float y = (acc[mt][nt][h * 2 + 1] + by[nt]) * inv;
                        red2(gb + col, x, y);
                    }
                }
        }
    }
}

/* ------------------------------ node GEMM + residual + relu ------------------------------ */
__global__ __launch_bounds__(256, 1) void k_node_mma(
    const float* __restrict__ b_node, const int* __restrict__ ntypes,
    float* __restrict__ out) {
    if ((int)blockIdx.x >= g_ntiles[1]) return;

    extern __shared__ float smf[];
    float* sA = smf;
    float* sB = smf + 128 * SROW;
    const uint32_t* sAu = (const uint32_t*)sA;
    const uint32_t* sBu = (const uint32_t*)sB;

    __shared__ int sNode[TILE];
    __shared__ float sBias[TILE];
    __shared__ int sNt;

    const int tid = threadIdx.x, wid = tid >> 5, lane = tid & 31;
    const int base = blockIdx.x * TILE;

    if (tid < TILE) {
        int n = g_nperm[base + tid];
        sNode[tid] = n;
        if (tid == 0) sNt = ntypes[n];
    }
    __syncthreads();
    const int nt_ = sNt;
    if (tid < TILE) sBias[tid] = b_node[nt_ * D + tid];

    {
        int r = tid >> 1, half = tid & 1;
        int n = sNode[r];
        const float4* fp = (const float4*)(g_featsR + (size_t)(n >= 0 ? n : 0) * D) + half * 16;
        float* ap = sA + r * SROW + half * 64;
#pragma unroll
        for (int i = 0; i < 16; i++) *(float4*)(ap + i * 4) = fp[i];
    }
    {
        const float* Wr = g_WnT + (size_t)nt_ * D * D;
#pragma unroll
        for (int i = 0; i < 16; i++) {
            int lin = tid + 256 * i;
            int f = lin >> 5, kq = lin & 31;
            *(float4*)(sB + f * SROW + kq * 4) = *(const float4*)(Wr + f * D + kq * 4);
        }
    }
    __syncthreads();

    const int wm = wid & 1, wn = wid >> 1;
    const int r_base = wm * 64, c_base = wn * 32;
    const int lq = lane >> 2, lr = lane & 3;

    float acc[4][4][4];
#pragma unroll
    for (int mt = 0; mt < 4; mt++)
#pragma unroll
        for (int ntl = 0; ntl < 4; ntl++)
#pragma unroll
            for (int j = 0; j < 4; j++) acc[mt][ntl][j] = 0.0f;

#pragma unroll 4
    for (int k0 = 0; k0 < 16; k0++) {
        const int kk = k0 * 8 + lr;
        uint32_t a[4][4], b[4][2];
#pragma unroll
        for (int mt = 0; mt < 4; mt++) {
            int row = r_base + mt * 16 + lq;
            a[mt][0] = sAu[row * SROW + kk];
            a[mt][1] = sAu[(row + 8) * SROW + kk];
            a[mt][2] = sAu[row * SROW + kk + 4];
            a[mt][3] = sAu[(row + 8) * SROW + kk + 4];
        }
#pragma unroll
        for (int ntl = 0; ntl < 4; ntl++) {
            int n = c_base + ntl * 8 + lq;
            b[ntl][0] = sBu[n * SROW + kk];
            b[ntl][1] = sBu[n * SROW + kk + 4];
        }
#pragma unroll
        for (int mt = 0; mt < 4; mt++)
#pragma unroll
            for (int ntl = 0; ntl < 4; ntl++) mma8(acc[mt][ntl], a[mt], b[ntl]);
    }

#pragma unroll
    for (int mt = 0; mt < 4; mt++) {
        int row0 = r_base + mt * 16 + lq;
#pragma unroll
        for (int h = 0; h < 2; h++) {
            int rr = row0 + h * 8;
            int n = sNode[rr];
            if (n < 0) continue;
            const float* ab = g_agg + (size_t)n * D;
            float* ob = out + (size_t)n * D;
#pragma unroll
            for (int ntl = 0; ntl < 4; ntl++) {
                int col = c_base + ntl * 8 + lr * 2;
                float2 ag = *(const float2*)(ab + col);
                float2 o;
                o.x = fmaxf(acc[mt][ntl][h * 2 + 0] + sBias[col] + ag.x, 0.0f);
                o.y = fmaxf(acc[mt][ntl][h * 2 + 1] + sBias[col + 1] + ag.y, 0.0f);
                *(float2*)(ob + col) = o;
            }
        }
    }
}

/* ------------------------------ launch ------------------------------ */
extern "C" void kernel_launch(void* const* d_in, const int* in_sizes, int n_in,
                              void* d_out, int out_size) {
    const float* feats  = (const float*)d_in[0];
    const float* W_edge = (const float*)d_in[1];
    const float* b_edge = (const float*)d_in[2];
    const float* W_node = (const float*)d_in[3];
    const float* b_node = (const float*)d_in[4];
    const int* src    = (const int*)d_in[5];
    const int* dst    = (const int*)d_in[6];
    const int* ntypes = (const int*)d_in[7];
    const int* etypes = (const int*)d_in[8];
    float* out = (float*)d_out;
    (void)in_sizes; (void)n_in; (void)out_size;

    cudaFuncSetAttribute(k_edge_p, cudaFuncAttributeMaxDynamicSharedMemorySize, EDGE_SMEM);
    cudaFuncSetAttribute(k_node_mma, cudaFuncAttributeMaxDynamicSharedMemorySize, NODE_SMEM);

    k_zerowt<<<1024, 256>>>(feats, W_edge, W_node);
    k_sortall<<<EDGE_GRID, 256>>>(dst, etypes, ntypes);
    k_nop<<<1, 1>>>();
    k_edge_p<<<EDGE_GRID, 512, EDGE_SMEM>>>(b_edge, src, dst, etypes);
    k_node_mma<<<NG, 256, NODE_SMEM>>>(b_node, ntypes, out);
}

// round 7
// speedup vs baseline: 1.2722x; 1.1543x over previous
#include <cuda_runtime.h>
#include <cstdint>

#define N_NODES 50000
#define N_EDGES 640000
#define D 128
#define N_RELS 16
#define N_NT 8
#define TILE 128

#define EG (N_EDGES / TILE + N_RELS)
#define NG ((N_NODES + TILE - 1) / TILE + N_NT)
#define E_PAD (EG * TILE)
#define N_PAD (NG * TILE)

#define SROW 136                          /* padded row stride: bank-clean for LDS.64 */
#define EDGE_SMEM (2 * 128 * SROW * 4)    /* sA + sB = 139264 B */
#define NSROW 132
#define NODE_SMEM (2 * 128 * NSROW * 4)
#define SETUP_GRID 148

/* ------------------------------ scratch ------------------------------ */
__device__ int   g_counts[N_NODES * N_RELS];
__device__ int   g_rel_cnt[N_RELS];
__device__ int   g_rel_cur[N_RELS];
__device__ int   g_nt_cnt[N_NT];
__device__ int   g_nt_cur[N_NT];
__device__ int   g_eperm[E_PAD];
__device__ int   g_esrc[E_PAD];
__device__ int   g_edst[E_PAD];
__device__ float g_einv[E_PAD];
__device__ int   g_erel[E_PAD];
__device__ int   g_nperm[N_PAD];
__device__ float g_agg[N_NODES * D];
__device__ int   g_ntiles[2];
__device__ float g_WT[N_RELS * D * D];   /* W_edge^T, tf32-rounded, pair-interleaved phi(k) */
__device__ float g_WnT[N_NT * D * D];    /* W_node^T, plain layout */
__device__ float g_featsR[N_NODES * D];
__device__ int   g_barrier_cnt;

/* ------------------------------ helpers ------------------------------ */
__device__ __forceinline__ uint32_t tf32r(float x) {
    uint32_t r;
    asm("cvt.rna.tf32.f32 %0, %1;" : "=r"(r) : "f"(x));
    return r;
}
__device__ __forceinline__ void mma8(float* c, const uint32_t* a, const uint32_t* b) {
    asm volatile(
        "mma.sync.aligned.m16n8k8.row.col.f32.tf32.tf32.f32 "
        "{%0,%1,%2,%3}, {%4,%5,%6,%7}, {%8,%9}, {%0,%1,%2,%3};"
        : "+f"(c[0]), "+f"(c[1]), "+f"(c[2]), "+f"(c[3])
        : "r"(a[0]), "r"(a[1]), "r"(a[2]), "r"(a[3]), "r"(b[0]), "r"(b[1]));
}
__device__ __forceinline__ void red2(float* p, float x, float y) {
    asm volatile("red.global.add.v2.f32 [%0], {%1,%2};" :: "l"(p), "f"(x), "f"(y) : "memory");
}
__device__ __forceinline__ void gsync(int phase) {
    __syncthreads();
    if (threadIdx.x == 0) {
        __threadfence();
        atomicAdd(&g_barrier_cnt, 1);
        while (atomicAdd(&g_barrier_cnt, 0) < SETUP_GRID * phase) {}
    }
    __syncthreads();
}
/* pair-interleave: phi(k) = (k>>3)*8 + (k&3)*2 + ((k>>2)&1) */
__device__ __forceinline__ int phik(int k) {
    return ((k >> 3) << 3) + ((k & 3) << 1) + ((k >> 2) & 1);
}

/* ------------------------------ setup: zero + round + transpose ------------------------------ */
__global__ void k_zerowt(const float* __restrict__ feats, const float* __restrict__ We,
                         const float* __restrict__ Wn) {
    int i = blockIdx.x * blockDim.x + threadIdx.x;
    int stride = gridDim.x * blockDim.x;
    for (int j = i; j < N_NODES * D; j += stride) {
        g_agg[j] = 0.0f;
        g_featsR[j] = __uint_as_float(tf32r(feats[j]));
    }
    for (int j = i; j < N_NODES * N_RELS; j += stride) g_counts[j] = 0;
    for (int j = i; j < E_PAD; j += stride) {
        g_edst[j] = -1;
        g_esrc[j] = 0;
        g_einv[j] = 0.0f;
    }
    for (int j = i; j < N_PAD; j += stride) g_nperm[j] = -1;
    if (i < N_RELS) g_rel_cnt[i] = 0;
    if (i < N_NT) g_nt_cnt[i] = 0;
    if (i == 0) g_barrier_cnt = 0;
    /* W_edge: transpose + tf32 round + phi-interleave k(=d) dim */
    for (int j = i; j < N_RELS * D * D; j += stride) {
        int m = j >> 14, lin = j & 16383;
        int f = lin >> 7, d = lin & 127;
        g_WT[(size_t)m * D * D + f * D + phik(d)] =
            __uint_as_float(tf32r(We[(size_t)m * D * D + d * D + f]));
    }
    /* W_node: transpose + round, plain layout */
    for (int j = i; j < N_NT * D * D; j += stride) {
        int m = j >> 14, lin = j & 16383;
        int f = lin >> 7, d = lin & 127;
        g_WnT[(size_t)m * D * D + f * D + d] =
            __uint_as_float(tf32r(Wn[(size_t)m * D * D + d * D + f]));
    }
}

/* ------------------------------ setup: hist + scan + scatter (+ per-edge meta) ------------------------------ */
__global__ __launch_bounds__(256, 1) void k_sortall(
    const int* __restrict__ src, const int* __restrict__ dst,
    const int* __restrict__ etypes, const int* __restrict__ ntypes) {
    __shared__ int sh[N_RELS + N_NT];
    __shared__ int s_cnt[N_RELS], s_base[N_RELS];
    const int tid = threadIdx.x;

    if (tid < N_RELS + N_NT) sh[tid] = 0;
    __syncthreads();
    int i = blockIdx.x * blockDim.x + tid;
    int stride = gridDim.x * blockDim.x;
    for (int e = i; e < N_EDGES; e += stride) {
        int t = etypes[e];
        atomicAdd(&sh[t], 1);
        atomicAdd(&g_counts[dst[e] * N_RELS + t], 1);
    }
    for (int n = i; n < N_NODES; n += stride) atomicAdd(&sh[N_RELS + ntypes[n]], 1);
    __syncthreads();
    if (tid < N_RELS) atomicAdd(&g_rel_cnt[tid], sh[tid]);
    else if (tid < N_RELS + N_NT) atomicAdd(&g_nt_cnt[tid - N_RELS], sh[tid]);

    gsync(1);

    if (blockIdx.x == 0 && tid == 0) {
        int off = 0;
        for (int t = 0; t < N_RELS; t++) {
            g_rel_cur[t] = off;
            off += ((g_rel_cnt[t] + TILE - 1) / TILE) * TILE;
        }
        g_ntiles[0] = off / TILE;
        off = 0;
        for (int t = 0; t < N_NT; t++) {
            g_nt_cur[t] = off;
            off += ((g_nt_cnt[t] + TILE - 1) / TILE) * TILE;
        }
        g_ntiles[1] = off / TILE;
        __threadfence();
    }

    gsync(2);

    const int CH = 2048;
    int nch = (N_EDGES + CH - 1) / CH;
    for (int ch = blockIdx.x; ch < nch; ch += gridDim.x) {
        int lo = ch * CH, hi = min(lo + CH, N_EDGES);
        if (tid < N_RELS) s_cnt[tid] = 0;
        __syncthreads();
        for (int e = lo + tid; e < hi; e += blockDim.x) atomicAdd(&s_cnt[etypes[e]], 1);
        __syncthreads();
        if (tid < N_RELS) {
            s_base[tid] = atomicAdd(&g_rel_cur[tid], s_cnt[tid]);
            s_cnt[tid] = 0;
        }
        __syncthreads();
        for (int e = lo + tid; e < hi; e += blockDim.x) {
            int t = etypes[e];
            int pos = s_base[t] + atomicAdd(&s_cnt[t], 1);
            int dn = dst[e];
            g_eperm[pos] = e;
            g_esrc[pos] = src[e];
            g_edst[pos] = dn;
            g_erel[pos] = t;
            g_einv[pos] = 1.0f / (float)g_counts[dn * N_RELS + t];
        }
        __syncthreads();
    }
    nch = (N_NODES + CH - 1) / CH;
    for (int ch = blockIdx.x; ch < nch; ch += gridDim.x) {
        int lo = ch * CH, hi = min(lo + CH, N_NODES);
        if (tid < N_NT) s_cnt[tid] = 0;
        __syncthreads();
        for (int n = lo + tid; n < hi; n += blockDim.x) atomicAdd(&s_cnt[ntypes[n]], 1);
        __syncthreads();
        if (tid < N_NT) {
            s_base[tid] = atomicAdd(&g_nt_cur[tid], s_cnt[tid]);
            s_cnt[tid] = 0;
        }
        __syncthreads();
        for (int n = lo + tid; n < hi; n += blockDim.x) {
            int t = ntypes[n];
            g_nperm[s_base[t] + atomicAdd(&s_cnt[t], 1)] = n;
        }
        __syncthreads();
    }
}

__global__ void k_nop() {}

/* ------------------------------ edge GEMM: one tile per CTA, 512 thr ------------------------------ */
/* Warp grid 4m x 4n, 32x32 warp tile. Paired-k smem layout -> float2 fragment loads.
 * 2 barriers total; epilogue fires red.v2 straight from accumulators. */
__global__ __launch_bounds__(512, 1) void k_edge_v7(const float* __restrict__ b_edge) {
    if ((int)blockIdx.x >= g_ntiles[0]) return;

    extern __shared__ float smf[];
    float* sA = smf;                   /* [128][SROW], phi-interleaved k */
    float* sB = smf + 128 * SROW;      /* [128][SROW], phi-interleaved k */

    __shared__ int sDst[TILE];
    __shared__ float sInv[TILE];
    __shared__ float sBias[TILE];
    __shared__ int sRel;

    const int tid = threadIdx.x;
    const int base = blockIdx.x * TILE;
    const int r = tid >> 2, q = tid & 3;

    /* coalesced meta */
    if (q == 0) {
        sDst[r] = g_edst[base + r];
        sInv[r] = g_einv[base + r];
    }
    if (tid == 0) sRel = g_erel[base]; /* row 0 of a live tile is always valid */

    /* gather A rows, interleaving pairs (k, k+4) in registers */
    {
        int s = g_esrc[base + r];
        const float4* fp = (const float4*)(g_featsR + (size_t)s * D);
        float* ap = sA + r * SROW;
#pragma unroll
        for (int i = 0; i < 4; i++) {
            int g = q * 4 + i;
            float4 v1 = fp[g * 2];       /* k = 8g .. 8g+3   */
            float4 v2 = fp[g * 2 + 1];   /* k = 8g+4 .. 8g+7 */
            float4 w1 = make_float4(v1.x, v2.x, v1.y, v2.y);
            float4 w2 = make_float4(v1.z, v2.z, v1.w, v2.w);
            *(float4*)(ap + g * 8) = w1;
            *(float4*)(ap + g * 8 + 4) = w2;
        }
    }
    __syncthreads();

    const int rel = sRel;
    /* B copy (already phi-interleaved in g_WT) */
    {
        const float* Wr = g_WT + (size_t)rel * D * D;
#pragma unroll
        for (int i = 0; i < 8; i++) {
            int lin = tid + 512 * i;
            int f = lin >> 5, wq = lin & 31;
            *(float4*)(sB + f * SROW + wq * 4) = *(const float4*)(Wr + f * D + wq * 4);
        }
    }
    if (tid < TILE) sBias[tid] = b_edge[rel * D + tid];
    __syncthreads();

    const int wid = tid >> 5, lane = tid & 31;
    const int wm = wid & 3, wn = wid >> 2;
    const int r_base = wm * 32, c_base = wn * 32;
    const int lq = lane >> 2, lr = lane & 3;

    float acc[2][4][4];
#pragma unroll
    for (int mt = 0; mt < 2; mt++)
#pragma unroll
        for (int nt = 0; nt < 4; nt++)
#pragma unroll
            for (int j = 0; j < 4; j++) acc[mt][nt][j] = 0.0f;

#pragma unroll 4
    for (int k0 = 0; k0 < 16; k0++) {
        const int kb = k0 * 8 + lr * 2;
        uint32_t a[2][4], bb[4][2];
#pragma unroll
        for (int mt = 0; mt < 2; mt++) {
            int row = r_base + mt * 16 + lq;
            float2 p0 = *(const float2*)(sA + row * SROW + kb);
            float2 p1 = *(const float2*)(sA + (row + 8) * SROW + kb);
            a[mt][0] = __float_as_uint(p0.x);
            a[mt][1] = __float_as_uint(p1.x);
            a[mt][2] = __float_as_uint(p0.y);
            a[mt][3] = __float_as_uint(p1.y);
        }
#pragma unroll
        for (int nt = 0; nt < 4; nt++) {
            int n = c_base + nt * 8 + lq;
            float2 pb = *(const float2*)(sB + n * SROW + kb);
            bb[nt][0] = __float_as_uint(pb.x);
            bb[nt][1] = __float_as_uint(pb.y);
        }
#pragma unroll
        for (int mt = 0; mt < 2; mt++)
#pragma unroll
            for (int nt = 0; nt < 4; nt++) mma8(acc[mt][nt], a[mt], bb[nt]);
    }

    /* epilogue: (acc + bias) * inv -> red.v2, no barrier */
#pragma unroll
    for (int mt = 0; mt < 2; mt++)
#pragma unroll
        for (int h = 0; h < 2; h++) {
            int rr = r_base + mt * 16 + lq + h * 8;
            int dn = sDst[rr];
            if (dn < 0) continue;
            float inv = sInv[rr];
            float* gb = g_agg + (size_t)dn * D;
#pragma unroll
            for (int nt = 0; nt < 4; nt++) {
                int col = c_base + nt * 8 + lr * 2;
                float x = (acc[mt][nt][h * 2 + 0] + sBias[col]) * inv;
                float y = (acc[mt][nt][h * 2 + 1] + sBias[col + 1]) * inv;
                red2(gb + col, x, y);
            }
        }
}

/* ------------------------------ node GEMM + residual + relu ------------------------------ */
__global__ __launch_bounds__(256, 1) void k_node_mma(
    const float* __restrict__ b_node, const int* __restrict__ ntypes,
    float* __restrict__ out) {
    if ((int)blockIdx.x >= g_ntiles[1]) return;

    extern __shared__ float smf[];
    float* sA = smf;
    float* sB = smf + 128 * NSROW;
    const uint32_t* sAu = (const uint32_t*)sA;
    const uint32_t* sBu = (const uint32_t*)sB;

    __shared__ int sNode[TILE];
    __shared__ float sBias[TILE];
    __shared__ int sNt;

    const int tid = threadIdx.x, wid = tid >> 5, lane = tid & 31;
    const int base = blockIdx.x * TILE;

    if (tid < TILE) {
        int n = g_nperm[base + tid];
        sNode[tid] = n;
        if (tid == 0) sNt = ntypes[n];
    }
    __syncthreads();
    const int nt_ = sNt;
    if (tid < TILE) sBias[tid] = b_node[nt_ * D + tid];

    {
        int r = tid >> 1, half = tid & 1;
        int n = sNode[r];
        const float4* fp = (const float4*)(g_featsR + (size_t)(n >= 0 ? n : 0) * D) + half * 16;
        float* ap = sA + r * NSROW + half * 64;
#pragma unroll
        for (int i = 0; i < 16; i++) *(float4*)(ap + i * 4) = fp[i];
    }
    {
        const float* Wr = g_WnT + (size_t)nt_ * D * D;
#pragma unroll
        for (int i = 0; i < 16; i++) {
            int lin = tid + 256 * i;
            int f = lin >> 5, kq = lin & 31;
            *(float4*)(sB + f * NSROW + kq * 4) = *(const float4*)(Wr + f * D + kq * 4);
        }
    }
    __syncthreads();

    const int wm = wid & 1, wn = wid >> 1;
    const int r_base = wm * 64, c_base = wn * 32;
    const int lq = lane >> 2, lr = lane & 3;

    float acc[4][4][4];
#pragma unroll
    for (int mt = 0; mt < 4; mt++)
#pragma unroll
        for (int ntl = 0; ntl < 4; ntl++)
#pragma unroll
            for (int j = 0; j < 4; j++) acc[mt][ntl][j] = 0.0f;

#pragma unroll 4
    for (int k0 = 0; k0 < 16; k0++) {
        const int kk = k0 * 8 + lr;
        uint32_t a[4][4], b[4][2];
#pragma unroll
        for (int mt = 0; mt < 4; mt++) {
            int row = r_base + mt * 16 + lq;
            a[mt][0] = sAu[row * NSROW + kk];
            a[mt][1] = sAu[(row + 8) * NSROW + kk];
            a[mt][2] = sAu[row * NSROW + kk + 4];
            a[mt][3] = sAu[(row + 8) * NSROW + kk + 4];
        }
#pragma unroll
        for (int ntl = 0; ntl < 4; ntl++) {
            int n = c_base + ntl * 8 + lq;
            b[ntl][0] = sBu[n * NSROW + kk];
            b[ntl][1] = sBu[n * NSROW + kk + 4];
        }
#pragma unroll
        for (int mt = 0; mt < 4; mt++)
#pragma unroll
            for (int ntl = 0; ntl < 4; ntl++) mma8(acc[mt][ntl], a[mt], b[ntl]);
    }

#pragma unroll
    for (int mt = 0; mt < 4; mt++) {
        int row0 = r_base + mt * 16 + lq;
#pragma unroll
        for (int h = 0; h < 2; h++) {
            int rr = row0 + h * 8;
            int n = sNode[rr];
            if (n < 0) continue;
            const float* ab = g_agg + (size_t)n * D;
            float* ob = out + (size_t)n * D;
#pragma unroll
            for (int ntl = 0; ntl < 4; ntl++) {
                int col = c_base + ntl * 8 + lr * 2;
                float2 ag = *(const float2*)(ab + col);
                float2 o;
                o.x = fmaxf(acc[mt][ntl][h * 2 + 0] + sBias[col] + ag.x, 0.0f);
                o.y = fmaxf(acc[mt][ntl][h * 2 + 1] + sBias[col + 1] + ag.y, 0.0f);
                *(float2*)(ob + col) = o;
            }
        }
    }
}

/* ------------------------------ launch ------------------------------ */
extern "C" void kernel_launch(void* const* d_in, const int* in_sizes, int n_in,
                              void* d_out, int out_size) {
    const float* feats  = (const float*)d_in[0];
    const float* W_edge = (const float*)d_in[1];
    const float* b_edge = (const float*)d_in[2];
    const float* W_node = (const float*)d_in[3];
    const float* b_node = (const float*)d_in[4];
    const int* src    = (const int*)d_in[5];
    const int* dst    = (const int*)d_in[6];
    const int* ntypes = (const int*)d_in[7];
    const int* etypes = (const int*)d_in[8];
    float* out = (float*)d_out;
    (void)in_sizes; (void)n_in; (void)out_size;

    cudaFuncSetAttribute(k_edge_v7, cudaFuncAttributeMaxDynamicSharedMemorySize, EDGE_SMEM);
    cudaFuncSetAttribute(k_node_mma, cudaFuncAttributeMaxDynamicSharedMemorySize, NODE_SMEM);

    k_zerowt<<<1024, 256>>>(feats, W_edge, W_node);
    k_sortall<<<SETUP_GRID, 256>>>(src, dst, etypes, ntypes);
    k_nop<<<1, 1>>>();
    k_edge_v7<<<EG, 512, EDGE_SMEM>>>(b_edge);
    k_node_mma<<<NG, 256, NODE_SMEM>>>(b_node, ntypes, out);
}